// round 1
// baseline (speedup 1.0000x reference)
#include <cuda_runtime.h>
#include <cuda_bf16.h>

#define NNODE 50000
#define F 128

// Scratch: 3 relation aggregation buffers + degree counters (sanctioned __device__ globals)
__device__ float g_agg[3ull * NNODE * F];   // [rel][node][feat]
__device__ float g_deg[3 * NNODE];
__device__ int   g_is64;

// ---------------------------------------------------------------------------
// Detect edge index dtype (int64 vs int32) deterministically from the data.
// int64 values < 50000 => every odd 32-bit word (high half) is 0.
// int32 random indices => some odd word among the first 1024 is nonzero.
// ---------------------------------------------------------------------------
__global__ void detect_kernel(const unsigned* __restrict__ w) {
    __shared__ int nz;
    if (threadIdx.x == 0) nz = 0;
    __syncthreads();
    unsigned v = w[2 * threadIdx.x + 1];
    if (v != 0) atomicOr(&nz, 1);
    __syncthreads();
    if (threadIdx.x == 0) g_is64 = (nz == 0);
}

// ---------------------------------------------------------------------------
// Zero scratch
// ---------------------------------------------------------------------------
__global__ void zero_kernel() {
    long long gid = (long long)blockIdx.x * blockDim.x + threadIdx.x;
    float4* a4 = (float4*)g_agg;
    if (gid < 3ll * NNODE * F / 4) a4[gid] = make_float4(0.f, 0.f, 0.f, 0.f);
    if (gid < 3 * NNODE) g_deg[gid] = 0.f;
}

// ---------------------------------------------------------------------------
// Scatter-add: one warp per edge. Lane i moves float4 #i of the 128-dim row.
// ---------------------------------------------------------------------------
__global__ void scatter_kernel(const void* __restrict__ edges, int E,
                               const float* __restrict__ xsrc, int rel) {
    int lane = threadIdx.x & 31;
    long long wid = ((long long)blockIdx.x * blockDim.x + threadIdx.x) >> 5;
    if (wid >= E) return;

    long long s, d;
    if (g_is64) {
        const long long* p = (const long long*)edges;
        s = p[wid];
        d = p[(long long)E + wid];
    } else {
        const int* p = (const int*)edges;
        s = p[wid];
        d = p[E + wid];
    }

    float4 v = ((const float4*)(xsrc + s * F))[lane];
    float* dst = g_agg + ((long long)rel * NNODE + d) * F + lane * 4;
    atomicAdd(dst + 0, v.x);
    atomicAdd(dst + 1, v.y);
    atomicAdd(dst + 2, v.z);
    atomicAdd(dst + 3, v.w);
    if (lane == 0) atomicAdd(g_deg + rel * NNODE + d, 1.0f);
}

// ---------------------------------------------------------------------------
// Fused multi-source GEMM:  out = relu( sum_s (A_s * rowscale_s) @ W_s + bias )
// rowscale_s = 1/max(deg_s,1) if deg pointer given, else 1.
// Tile: 64 rows x 128 cols per block, 256 threads, each thread 8x4 outputs.
// ---------------------------------------------------------------------------
template <int NSRC>
__global__ void __launch_bounds__(256) gemm_fused(
    const float* __restrict__ A0, const float* __restrict__ A1, const float* __restrict__ A2,
    const float* __restrict__ D0, const float* __restrict__ D1, const float* __restrict__ D2,
    const float* __restrict__ W0, const float* __restrict__ W1, const float* __restrict__ W2,
    const float* __restrict__ bias, float* __restrict__ out, int M)
{
    __shared__ float As[64][17];      // padded to dodge bank conflicts on stores
    __shared__ float Ws[16][128];
    __shared__ float scl[64];

    int tid = threadIdx.x;
    int tx = tid & 31;                // 32 column groups (4 cols each)
    int ty = tid >> 5;                // 8 row groups (8 rows each)
    int row0 = blockIdx.x * 64;

    float acc[8][4];
#pragma unroll
    for (int i = 0; i < 8; i++)
#pragma unroll
        for (int j = 0; j < 4; j++) acc[i][j] = 0.f;

#pragma unroll
    for (int s = 0; s < NSRC; s++) {
        const float* A = (s == 0) ? A0 : (s == 1) ? A1 : A2;
        const float* D = (s == 0) ? D0 : (s == 1) ? D1 : D2;
        const float* W = (s == 0) ? W0 : (s == 1) ? W1 : W2;

        // per-row normalization factor
        if (tid < 64) {
            float sc = 1.f;
            int r = row0 + tid;
            if (D != nullptr && r < M) sc = 1.f / fmaxf(D[r], 1.f);
            scl[tid] = sc;
        }
        __syncthreads();

        for (int k0 = 0; k0 < F; k0 += 16) {
            // load A tile 64x16 (scaled)
            int r = tid >> 2, c4 = tid & 3;
            float4 av = make_float4(0.f, 0.f, 0.f, 0.f);
            if (row0 + r < M)
                av = *(const float4*)(A + (long long)(row0 + r) * F + k0 + c4 * 4);
            float sc = scl[r];
            As[r][c4 * 4 + 0] = av.x * sc;
            As[r][c4 * 4 + 1] = av.y * sc;
            As[r][c4 * 4 + 2] = av.z * sc;
            As[r][c4 * 4 + 3] = av.w * sc;

            // load W tile 16x128 (512 float4, 2 per thread)
#pragma unroll
            for (int t = 0; t < 2; t++) {
                int idx4 = tid + t * 256;
                int kk = idx4 >> 5, n4 = idx4 & 31;
                float4 wv = *(const float4*)(W + (long long)(k0 + kk) * F + n4 * 4);
                *(float4*)&Ws[kk][n4 * 4] = wv;
            }
            __syncthreads();

#pragma unroll
            for (int kk = 0; kk < 16; kk++) {
                float b0 = Ws[kk][tx * 4 + 0];
                float b1 = Ws[kk][tx * 4 + 1];
                float b2 = Ws[kk][tx * 4 + 2];
                float b3 = Ws[kk][tx * 4 + 3];
#pragma unroll
                for (int i = 0; i < 8; i++) {
                    float a = As[ty * 8 + i][kk];   // broadcast within warp
                    acc[i][0] += a * b0;
                    acc[i][1] += a * b1;
                    acc[i][2] += a * b2;
                    acc[i][3] += a * b3;
                }
            }
            __syncthreads();
        }
    }

    // epilogue: bias + relu + store
    float bv0 = bias[tx * 4 + 0];
    float bv1 = bias[tx * 4 + 1];
    float bv2 = bias[tx * 4 + 2];
    float bv3 = bias[tx * 4 + 3];
#pragma unroll
    for (int i = 0; i < 8; i++) {
        int r = row0 + ty * 8 + i;
        if (r < M) {
            float4 o;
            o.x = fmaxf(acc[i][0] + bv0, 0.f);
            o.y = fmaxf(acc[i][1] + bv1, 0.f);
            o.z = fmaxf(acc[i][2] + bv2, 0.f);
            o.w = fmaxf(acc[i][3] + bv3, 0.f);
            *(float4*)(out + (long long)r * F + tx * 4) = o;
        }
    }
}

// ---------------------------------------------------------------------------
extern "C" void kernel_launch(void* const* d_in, const int* in_sizes, int n_in,
                              void* d_out, int out_size) {
    const float* x_user = (const float*)d_in[0];
    const float* x_item = (const float*)d_in[1];
    const void* e_follows   = d_in[2];
    const void* e_buys      = d_in[3];
    const void* e_bought_by = d_in[4];
    const float* W_follows   = (const float*)d_in[5];
    const float* W_buys      = (const float*)d_in[6];
    const float* W_bought_by = (const float*)d_in[7];
    const float* W_loop_user = (const float*)d_in[8];
    const float* b_loop_user = (const float*)d_in[9];
    const float* W_loop_item = (const float*)d_in[10];
    const float* b_loop_item = (const float*)d_in[11];

    int Ef  = in_sizes[2] / 2;
    int Eb  = in_sizes[3] / 2;
    int Ebb = in_sizes[4] / 2;

    float* agg;
    float* deg;
    cudaGetSymbolAddress((void**)&agg, g_agg);
    cudaGetSymbolAddress((void**)&deg, g_deg);

    detect_kernel<<<1, 1024>>>((const unsigned*)e_follows);

    {
        long long n4 = 3ll * NNODE * F / 4;   // 4.8M float4
        int blocks = (int)((n4 + 255) / 256);
        zero_kernel<<<blocks, 256>>>();
    }

    auto sblocks = [](int E) { return (int)(((long long)E * 32 + 255) / 256); };
    // rel 0: follows    (user -> user)
    scatter_kernel<<<sblocks(Ef), 256>>>(e_follows, Ef, x_user, 0);
    // rel 1: bought_by  (item -> user)
    scatter_kernel<<<sblocks(Ebb), 256>>>(e_bought_by, Ebb, x_item, 1);
    // rel 2: buys       (user -> item)
    scatter_kernel<<<sblocks(Eb), 256>>>(e_buys, Eb, x_user, 2);

    float* out_user = (float*)d_out;
    float* out_item = (float*)d_out + (long long)NNODE * F;

    int gblocks = (NNODE + 63) / 64;
    // h_user = relu(aggF/degF @ W_f + aggBB/degBB @ W_bb + x_user @ W_loop_user + b)
    gemm_fused<3><<<gblocks, 256>>>(
        agg, agg + 1ll * NNODE * F, x_user,
        deg, deg + NNODE, nullptr,
        W_follows, W_bought_by, W_loop_user,
        b_loop_user, out_user, NNODE);
    // h_item = relu(aggBuys/degBuys @ W_buys + x_item @ W_loop_item + b)
    gemm_fused<2><<<gblocks, 256>>>(
        agg + 2ll * NNODE * F, x_item, nullptr,
        deg + 2 * NNODE, nullptr, nullptr,
        W_buys, W_loop_item, nullptr,
        b_loop_item, out_item, NNODE);
}

// round 2
// speedup vs baseline: 1.5677x; 1.5677x over previous
#include <cuda_runtime.h>
#include <cuda_bf16.h>

#define NNODE 50000
#define F 128

// Scratch: 3 relation aggregation buffers + degree counters (sanctioned __device__ globals)
__device__ float g_agg[3ull * NNODE * F];   // [rel][node][feat]
__device__ float g_deg[3 * NNODE];
__device__ int   g_is64;

// ---------------------------------------------------------------------------
// Detect edge index dtype (int64 vs int32) deterministically from the data.
// int64 values < 50000 => every odd 32-bit word (high half) is 0.
// ---------------------------------------------------------------------------
__global__ void detect_kernel(const unsigned* __restrict__ w) {
    __shared__ int nz;
    if (threadIdx.x == 0) nz = 0;
    __syncthreads();
    unsigned v = w[2 * threadIdx.x + 1];
    if (v != 0) atomicOr(&nz, 1);
    __syncthreads();
    if (threadIdx.x == 0) g_is64 = (nz == 0);
}

// ---------------------------------------------------------------------------
// Zero scratch
// ---------------------------------------------------------------------------
__global__ void zero_kernel() {
    long long gid = (long long)blockIdx.x * blockDim.x + threadIdx.x;
    float4* a4 = (float4*)g_agg;
    if (gid < 3ll * NNODE * F / 4) a4[gid] = make_float4(0.f, 0.f, 0.f, 0.f);
    if (gid < 3 * NNODE) g_deg[gid] = 0.f;
}

// ---------------------------------------------------------------------------
// Scatter-add: one warp per edge. Lane i moves float4 #i of the 128-dim row.
// Uses red.global.add.v4.f32 (sm_90+): 1 atomic instruction per 16 bytes
// instead of 4 scalar atomicAdds -> 4x fewer L1tex wavefronts / LSU issues.
// ---------------------------------------------------------------------------
__global__ void scatter_kernel(const void* __restrict__ edges, int E,
                               const float* __restrict__ xsrc, int rel) {
    int lane = threadIdx.x & 31;
    long long wid = ((long long)blockIdx.x * blockDim.x + threadIdx.x) >> 5;
    if (wid >= E) return;

    long long s, d;
    if (g_is64) {
        const long long* p = (const long long*)edges;
        s = p[wid];
        d = p[(long long)E + wid];
    } else {
        const int* p = (const int*)edges;
        s = p[wid];
        d = p[E + wid];
    }

    float4 v = __ldg((const float4*)(xsrc + s * F) + lane);
    float* dst = g_agg + ((long long)rel * NNODE + d) * F + lane * 4;
    asm volatile("red.global.add.v4.f32 [%0], {%1, %2, %3, %4};"
                 :: "l"(dst), "f"(v.x), "f"(v.y), "f"(v.z), "f"(v.w)
                 : "memory");
    if (lane == 0) atomicAdd(g_deg + rel * NNODE + d, 1.0f);
}

// ---------------------------------------------------------------------------
// Fused multi-source GEMM:  out = relu( sum_s (A_s * rowscale_s) @ W_s + bias )
// rowscale_s = 1/max(deg_s,1) if deg pointer given, else 1.
// Tile: 64 rows x 128 cols per block, 256 threads, each thread 8x4 outputs.
// ---------------------------------------------------------------------------
template <int NSRC>
__global__ void __launch_bounds__(256) gemm_fused(
    const float* __restrict__ A0, const float* __restrict__ A1, const float* __restrict__ A2,
    const float* __restrict__ D0, const float* __restrict__ D1, const float* __restrict__ D2,
    const float* __restrict__ W0, const float* __restrict__ W1, const float* __restrict__ W2,
    const float* __restrict__ bias, float* __restrict__ out, int M)
{
    __shared__ float As[64][17];      // padded to dodge bank conflicts on stores
    __shared__ float Ws[16][128];
    __shared__ float scl[64];

    int tid = threadIdx.x;
    int tx = tid & 31;                // 32 column groups (4 cols each)
    int ty = tid >> 5;                // 8 row groups (8 rows each)
    int row0 = blockIdx.x * 64;

    float acc[8][4];
#pragma unroll
    for (int i = 0; i < 8; i++)
#pragma unroll
        for (int j = 0; j < 4; j++) acc[i][j] = 0.f;

#pragma unroll
    for (int s = 0; s < NSRC; s++) {
        const float* A = (s == 0) ? A0 : (s == 1) ? A1 : A2;
        const float* D = (s == 0) ? D0 : (s == 1) ? D1 : D2;
        const float* W = (s == 0) ? W0 : (s == 1) ? W1 : W2;

        // per-row normalization factor
        if (tid < 64) {
            float sc = 1.f;
            int r = row0 + tid;
            if (D != nullptr && r < M) sc = 1.f / fmaxf(D[r], 1.f);
            scl[tid] = sc;
        }
        __syncthreads();

        for (int k0 = 0; k0 < F; k0 += 16) {
            // load A tile 64x16 (scaled)
            int r = tid >> 2, c4 = tid & 3;
            float4 av = make_float4(0.f, 0.f, 0.f, 0.f);
            if (row0 + r < M)
                av = *(const float4*)(A + (long long)(row0 + r) * F + k0 + c4 * 4);
            float sc = scl[r];
            As[r][c4 * 4 + 0] = av.x * sc;
            As[r][c4 * 4 + 1] = av.y * sc;
            As[r][c4 * 4 + 2] = av.z * sc;
            As[r][c4 * 4 + 3] = av.w * sc;

            // load W tile 16x128 (512 float4, 2 per thread)
#pragma unroll
            for (int t = 0; t < 2; t++) {
                int idx4 = tid + t * 256;
                int kk = idx4 >> 5, n4 = idx4 & 31;
                float4 wv = *(const float4*)(W + (long long)(k0 + kk) * F + n4 * 4);
                *(float4*)&Ws[kk][n4 * 4] = wv;
            }
            __syncthreads();

#pragma unroll
            for (int kk = 0; kk < 16; kk++) {
                float b0 = Ws[kk][tx * 4 + 0];
                float b1 = Ws[kk][tx * 4 + 1];
                float b2 = Ws[kk][tx * 4 + 2];
                float b3 = Ws[kk][tx * 4 + 3];
#pragma unroll
                for (int i = 0; i < 8; i++) {
                    float a = As[ty * 8 + i][kk];   // broadcast within warp
                    acc[i][0] += a * b0;
                    acc[i][1] += a * b1;
                    acc[i][2] += a * b2;
                    acc[i][3] += a * b3;
                }
            }
            __syncthreads();
        }
    }

    // epilogue: bias + relu + store
    float bv0 = bias[tx * 4 + 0];
    float bv1 = bias[tx * 4 + 1];
    float bv2 = bias[tx * 4 + 2];
    float bv3 = bias[tx * 4 + 3];
#pragma unroll
    for (int i = 0; i < 8; i++) {
        int r = row0 + ty * 8 + i;
        if (r < M) {
            float4 o;
            o.x = fmaxf(acc[i][0] + bv0, 0.f);
            o.y = fmaxf(acc[i][1] + bv1, 0.f);
            o.z = fmaxf(acc[i][2] + bv2, 0.f);
            o.w = fmaxf(acc[i][3] + bv3, 0.f);
            *(float4*)(out + (long long)r * F + tx * 4) = o;
        }
    }
}

// ---------------------------------------------------------------------------
extern "C" void kernel_launch(void* const* d_in, const int* in_sizes, int n_in,
                              void* d_out, int out_size) {
    const float* x_user = (const float*)d_in[0];
    const float* x_item = (const float*)d_in[1];
    const void* e_follows   = d_in[2];
    const void* e_buys      = d_in[3];
    const void* e_bought_by = d_in[4];
    const float* W_follows   = (const float*)d_in[5];
    const float* W_buys      = (const float*)d_in[6];
    const float* W_bought_by = (const float*)d_in[7];
    const float* W_loop_user = (const float*)d_in[8];
    const float* b_loop_user = (const float*)d_in[9];
    const float* W_loop_item = (const float*)d_in[10];
    const float* b_loop_item = (const float*)d_in[11];

    int Ef  = in_sizes[2] / 2;
    int Eb  = in_sizes[3] / 2;
    int Ebb = in_sizes[4] / 2;

    float* agg;
    float* deg;
    cudaGetSymbolAddress((void**)&agg, g_agg);
    cudaGetSymbolAddress((void**)&deg, g_deg);

    detect_kernel<<<1, 1024>>>((const unsigned*)e_follows);

    {
        long long n4 = 3ll * NNODE * F / 4;   // 4.8M float4
        int blocks = (int)((n4 + 255) / 256);
        zero_kernel<<<blocks, 256>>>();
    }

    auto sblocks = [](int E) { return (int)(((long long)E * 32 + 255) / 256); };
    // rel 0: follows    (user -> user)
    scatter_kernel<<<sblocks(Ef), 256>>>(e_follows, Ef, x_user, 0);
    // rel 1: bought_by  (item -> user)
    scatter_kernel<<<sblocks(Ebb), 256>>>(e_bought_by, Ebb, x_item, 1);
    // rel 2: buys       (user -> item)
    scatter_kernel<<<sblocks(Eb), 256>>>(e_buys, Eb, x_user, 2);

    float* out_user = (float*)d_out;
    float* out_item = (float*)d_out + (long long)NNODE * F;

    int gblocks = (NNODE + 63) / 64;
    // h_user = relu(aggF/degF @ W_f + aggBB/degBB @ W_bb + x_user @ W_loop_user + b)
    gemm_fused<3><<<gblocks, 256>>>(
        agg, agg + 1ll * NNODE * F, x_user,
        deg, deg + NNODE, nullptr,
        W_follows, W_bought_by, W_loop_user,
        b_loop_user, out_user, NNODE);
    // h_item = relu(aggBuys/degBuys @ W_buys + x_item @ W_loop_item + b)
    gemm_fused<2><<<gblocks, 256>>>(
        agg + 2ll * NNODE * F, x_item, nullptr,
        deg + 2 * NNODE, nullptr, nullptr,
        W_buys, W_loop_item, nullptr,
        b_loop_item, out_item, NNODE);
}

// round 4
// speedup vs baseline: 1.7895x; 1.1415x over previous
#include <cuda_runtime.h>
#include <cuda_bf16.h>
#include <cstdint>

#define NNODE 50000
#define F 128

// Scratch (sanctioned __device__ globals)
__device__ float g_agg[3ull * NNODE * F];   // [rel][node][feat]
__device__ float g_deg[3 * NNODE];
__device__ __nv_bfloat16 g_WThi[5ull * F * F];  // WT hi: [slot][n][k] = bf16(W[k][n])
__device__ __nv_bfloat16 g_WTlo[5ull * F * F];  // WT lo: residual
__device__ int   g_is64;

// ---------------------------------------------------------------------------
// dtype detection (int64 vs int32 edge indices)
// ---------------------------------------------------------------------------
__global__ void detect_kernel(const unsigned* __restrict__ w) {
    __shared__ int nz;
    if (threadIdx.x == 0) nz = 0;
    __syncthreads();
    if (w[2 * threadIdx.x + 1] != 0) atomicOr(&nz, 1);
    __syncthreads();
    if (threadIdx.x == 0) g_is64 = (nz == 0);
}

// ---------------------------------------------------------------------------
__global__ void zero_kernel() {
    long long gid = (long long)blockIdx.x * blockDim.x + threadIdx.x;
    float4* a4 = (float4*)g_agg;
    if (gid < 3ll * NNODE * F / 4) a4[gid] = make_float4(0.f, 0.f, 0.f, 0.f);
    if (gid < 3 * NNODE) g_deg[gid] = 0.f;
}

// ---------------------------------------------------------------------------
// Transpose + bf16 hi/lo split of the 5 weight matrices.
// WThi[b][n][k] = bf16(W_b[k][n]);  WTlo = bf16(W_b[k][n] - hi)
// ---------------------------------------------------------------------------
__global__ void convW_kernel(const float* __restrict__ W0, const float* __restrict__ W1,
                             const float* __restrict__ W2, const float* __restrict__ W3,
                             const float* __restrict__ W4) {
    const float* W = (blockIdx.x == 0) ? W0 : (blockIdx.x == 1) ? W1 :
                     (blockIdx.x == 2) ? W2 : (blockIdx.x == 3) ? W3 : W4;
    __nv_bfloat16* hi = g_WThi + (size_t)blockIdx.x * F * F;
    __nv_bfloat16* lo = g_WTlo + (size_t)blockIdx.x * F * F;
    for (int idx = threadIdx.x; idx < F * F; idx += blockDim.x) {
        int k = idx >> 7, n = idx & 127;
        float v = W[idx];
        __nv_bfloat16 h = __float2bfloat16(v);
        float r = v - __bfloat162float(h);
        hi[n * F + k] = h;
        lo[n * F + k] = __float2bfloat16(r);
    }
}

// ---------------------------------------------------------------------------
// Merged scatter: one warp per edge across all 3 relations. red.v4 atomics.
// ---------------------------------------------------------------------------
__global__ void scatter_all(const void* __restrict__ e0, const void* __restrict__ e1,
                            const void* __restrict__ e2, int E0, int E1, int E2,
                            const float* __restrict__ xu, const float* __restrict__ xi) {
    int lane = threadIdx.x & 31;
    long long wid = ((long long)blockIdx.x * blockDim.x + threadIdx.x) >> 5;
    const void* e; const float* x; int rel; long long ew; int E;
    if (wid < E0)                           { e = e0; x = xu; rel = 0; ew = wid;            E = E0; }
    else if (wid < (long long)E0 + E1)      { e = e1; x = xi; rel = 1; ew = wid - E0;       E = E1; }
    else if (wid < (long long)E0 + E1 + E2) { e = e2; x = xu; rel = 2; ew = wid - E0 - E1;  E = E2; }
    else return;

    long long s, d;
    if (g_is64) {
        const long long* p = (const long long*)e;
        s = p[ew]; d = p[(long long)E + ew];
    } else {
        const int* p = (const int*)e;
        s = p[ew]; d = p[E + ew];
    }

    float4 v = __ldg((const float4*)(x + s * F) + lane);
    float* dst = g_agg + ((long long)rel * NNODE + d) * F + lane * 4;
    asm volatile("red.global.add.v4.f32 [%0], {%1, %2, %3, %4};"
                 :: "l"(dst), "f"(v.x), "f"(v.y), "f"(v.z), "f"(v.w) : "memory");
    if (lane == 0) atomicAdd(g_deg + rel * NNODE + d, 1.0f);
}

// ---------------------------------------------------------------------------
// Tensor-core GEMM via mma.sync bf16 with 3-term split:
//   out = relu( sum_s diag(1/max(deg_s,1)) * A_s @ W_s + bias )
// CTA tile 128x128, 8 warps in 2x4, warp tile 64x32, atoms m16n8k16.
// K chunked by 32; A split hi/lo on the fly; W pre-split in g_WThi/lo.
// smem rows padded to 40 bf16 (20 words) => conflict-free LDS32 fragments.
// ---------------------------------------------------------------------------
#define ASTRIDE 40

__device__ __forceinline__ void mma_bf16(float& c0, float& c1, float& c2, float& c3,
                                         uint32_t a0, uint32_t a1, uint32_t a2, uint32_t a3,
                                         uint32_t b0, uint32_t b1) {
    asm volatile(
        "mma.sync.aligned.m16n8k16.row.col.f32.bf16.bf16.f32 "
        "{%0,%1,%2,%3}, {%4,%5,%6,%7}, {%8,%9}, {%0,%1,%2,%3};"
        : "+f"(c0), "+f"(c1), "+f"(c2), "+f"(c3)
        : "r"(a0), "r"(a1), "r"(a2), "r"(a3), "r"(b0), "r"(b1));
}

template <int NSRC>
__global__ void __launch_bounds__(256, 2) gemm_mma(
    const float* __restrict__ A0, const float* __restrict__ A1, const float* __restrict__ A2,
    const float* __restrict__ D0, const float* __restrict__ D1, const float* __restrict__ D2,
    const __nv_bfloat16* __restrict__ Bh0, const __nv_bfloat16* __restrict__ Bh1,
    const __nv_bfloat16* __restrict__ Bh2,
    const __nv_bfloat16* __restrict__ Bl0, const __nv_bfloat16* __restrict__ Bl1,
    const __nv_bfloat16* __restrict__ Bl2,
    const float* __restrict__ bias, float* __restrict__ out, int M)
{
    __shared__ __nv_bfloat16 sAhi[128 * ASTRIDE];
    __shared__ __nv_bfloat16 sAlo[128 * ASTRIDE];
    __shared__ __nv_bfloat16 sBhi[128 * ASTRIDE];
    __shared__ __nv_bfloat16 sBlo[128 * ASTRIDE];
    __shared__ float scl[128];

    const int tid = threadIdx.x;
    const int w = tid >> 5, l = tid & 31;
    const int mBase = (w >> 2) * 64;
    const int nBase = (w & 3) * 32;
    const int row0 = blockIdx.x * 128;
    const int lq = l >> 2;          // 0..7
    const int lr2 = (l & 3) * 2;    // 0,2,4,6

    float acc[4][4][4];
#pragma unroll
    for (int i = 0; i < 4; i++)
#pragma unroll
        for (int j = 0; j < 4; j++)
#pragma unroll
            for (int q = 0; q < 4; q++) acc[i][j][q] = 0.f;

#pragma unroll
    for (int s = 0; s < NSRC; s++) {
        const float* A = (s == 0) ? A0 : (s == 1) ? A1 : A2;
        const float* D = (s == 0) ? D0 : (s == 1) ? D1 : D2;
        const __nv_bfloat16* Bh = (s == 0) ? Bh0 : (s == 1) ? Bh1 : Bh2;
        const __nv_bfloat16* Bl = (s == 0) ? Bl0 : (s == 1) ? Bl1 : Bl2;

        if (tid < 128) {
            float sc = 1.f;
            int r = row0 + tid;
            if (D != nullptr && r < M) sc = 1.f / fmaxf(D[r], 1.f);
            scl[tid] = sc;
        }
        __syncthreads();

        for (int ks = 0; ks < F; ks += 32) {
            // ---- stage A chunk [128 x 32] fp32 -> scaled hi/lo bf16 ----
#pragma unroll
            for (int t = 0; t < 4; t++) {
                int idx = t * 256 + tid;       // 1024 float4 slots
                int r = idx >> 3, c4 = idx & 7;
                float4 v = make_float4(0.f, 0.f, 0.f, 0.f);
                int gr = row0 + r;
                if (gr < M) v = __ldg((const float4*)(A + (size_t)gr * F + ks) + c4);
                float sc = scl[r];
                v.x *= sc; v.y *= sc; v.z *= sc; v.w *= sc;
                __nv_bfloat16 hx = __float2bfloat16(v.x), hy = __float2bfloat16(v.y);
                __nv_bfloat16 hz = __float2bfloat16(v.z), hw = __float2bfloat16(v.w);
                __nv_bfloat162 h01{hx, hy}, h23{hz, hw};
                __nv_bfloat162 l01{__float2bfloat16(v.x - __bfloat162float(hx)),
                                   __float2bfloat16(v.y - __bfloat162float(hy))};
                __nv_bfloat162 l23{__float2bfloat16(v.z - __bfloat162float(hz)),
                                   __float2bfloat16(v.w - __bfloat162float(hw))};
                int o = r * ASTRIDE + c4 * 4;
                *(__nv_bfloat162*)&sAhi[o] = h01;  *(__nv_bfloat162*)&sAhi[o + 2] = h23;
                *(__nv_bfloat162*)&sAlo[o] = l01;  *(__nv_bfloat162*)&sAlo[o + 2] = l23;
            }
            // ---- stage B chunk [128n x 32k] bf16 hi/lo (pre-split) ----
#pragma unroll
            for (int t = 0; t < 4; t++) {
                int idx = t * 256 + tid;       // 1024 uint2 slots (4 bf16 each)
                int n = idx >> 3, c4 = idx & 7;
                uint2 hv = *(const uint2*)(Bh + (size_t)n * F + ks + c4 * 4);
                uint2 lv = *(const uint2*)(Bl + (size_t)n * F + ks + c4 * 4);
                int o = n * ASTRIDE + c4 * 4;
                *(uint2*)&sBhi[o] = hv;
                *(uint2*)&sBlo[o] = lv;
            }
            __syncthreads();

            // ---- mma: 2 k-steps x 3 terms x 16 atoms ----
#pragma unroll
            for (int kk = 0; kk < 32; kk += 16) {
#pragma unroll
                for (int term = 0; term < 3; term++) {
                    const __nv_bfloat16* pA = (term == 1) ? sAlo : sAhi;
                    const __nv_bfloat16* pB = (term == 2) ? sBlo : sBhi;
                    uint32_t a[4][4], b[4][2];
#pragma unroll
                    for (int i = 0; i < 4; i++) {
                        int ar = mBase + i * 16 + lq;
                        int ac = kk + lr2;
                        a[i][0] = *(const uint32_t*)&pA[ar * ASTRIDE + ac];
                        a[i][1] = *(const uint32_t*)&pA[(ar + 8) * ASTRIDE + ac];
                        a[i][2] = *(const uint32_t*)&pA[ar * ASTRIDE + ac + 8];
                        a[i][3] = *(const uint32_t*)&pA[(ar + 8) * ASTRIDE + ac + 8];
                    }
#pragma unroll
                    for (int j = 0; j < 4; j++) {
                        int bn = nBase + j * 8 + lq;
                        int bk = kk + lr2;
                        b[j][0] = *(const uint32_t*)&pB[bn * ASTRIDE + bk];
                        b[j][1] = *(const uint32_t*)&pB[bn * ASTRIDE + bk + 8];
                    }
#pragma unroll
                    for (int i = 0; i < 4; i++)
#pragma unroll
                        for (int j = 0; j < 4; j++)
                            mma_bf16(acc[i][j][0], acc[i][j][1], acc[i][j][2], acc[i][j][3],
                                     a[i][0], a[i][1], a[i][2], a[i][3], b[j][0], b[j][1]);
                }
            }
            __syncthreads();
        }
    }

    // ---- epilogue: bias + relu + store ----
#pragma unroll
    for (int j = 0; j < 4; j++) {
        int col = nBase + j * 8 + lr2;
        float2 bv = *(const float2*)(bias + col);
#pragma unroll
        for (int i = 0; i < 4; i++) {
            int r0 = row0 + mBase + i * 16 + lq;
            int r1 = r0 + 8;
            if (r0 < M) {
                float2 o0;
                o0.x = fmaxf(acc[i][j][0] + bv.x, 0.f);
                o0.y = fmaxf(acc[i][j][1] + bv.y, 0.f);
                *(float2*)(out + (size_t)r0 * F + col) = o0;
            }
            if (r1 < M) {
                float2 o1;
                o1.x = fmaxf(acc[i][j][2] + bv.x, 0.f);
                o1.y = fmaxf(acc[i][j][3] + bv.y, 0.f);
                *(float2*)(out + (size_t)r1 * F + col) = o1;
            }
        }
    }
}

// ---------------------------------------------------------------------------
extern "C" void kernel_launch(void* const* d_in, const int* in_sizes, int n_in,
                              void* d_out, int out_size) {
    const float* x_user = (const float*)d_in[0];
    const float* x_item = (const float*)d_in[1];
    const void* e_follows   = d_in[2];
    const void* e_buys      = d_in[3];
    const void* e_bought_by = d_in[4];
    const float* W_follows   = (const float*)d_in[5];
    const float* W_buys      = (const float*)d_in[6];
    const float* W_bought_by = (const float*)d_in[7];
    const float* W_loop_user = (const float*)d_in[8];
    const float* b_loop_user = (const float*)d_in[9];
    const float* W_loop_item = (const float*)d_in[10];
    const float* b_loop_item = (const float*)d_in[11];

    int Ef  = in_sizes[2] / 2;
    int Eb  = in_sizes[3] / 2;
    int Ebb = in_sizes[4] / 2;

    float* agg; float* deg;
    __nv_bfloat16* wth; __nv_bfloat16* wtl;
    cudaGetSymbolAddress((void**)&agg, g_agg);
    cudaGetSymbolAddress((void**)&deg, g_deg);
    cudaGetSymbolAddress((void**)&wth, g_WThi);
    cudaGetSymbolAddress((void**)&wtl, g_WTlo);

    detect_kernel<<<1, 1024>>>((const unsigned*)e_follows);

    {
        long long n4 = 3ll * NNODE * F / 4;
        zero_kernel<<<(int)((n4 + 255) / 256), 256>>>();
    }
    // slots: 0=follows, 1=bought_by, 2=loop_user, 3=buys, 4=loop_item
    convW_kernel<<<5, 256>>>(W_follows, W_bought_by, W_loop_user, W_buys, W_loop_item);

    {
        long long totw = (long long)Ef + Ebb + Eb;
        int blocks = (int)((totw * 32 + 255) / 256);
        scatter_all<<<blocks, 256>>>(e_follows, e_bought_by, e_buys,
                                     Ef, Ebb, Eb, x_user, x_item);
    }

    float* out_user = (float*)d_out;
    float* out_item = (float*)d_out + (size_t)NNODE * F;
    int gblocks = (NNODE + 127) / 128;   // 391
    const size_t FF = (size_t)F * F;

    gemm_mma<3><<<gblocks, 256>>>(
        agg, agg + 1ll * NNODE * F, x_user,
        deg, deg + NNODE, nullptr,
        wth + 0 * FF, wth + 1 * FF, wth + 2 * FF,
        wtl + 0 * FF, wtl + 1 * FF, wtl + 2 * FF,
        b_loop_user, out_user, NNODE);

    gemm_mma<2><<<gblocks, 256>>>(
        agg + 2ll * NNODE * F, x_item, nullptr,
        deg + 2 * NNODE, nullptr, nullptr,
        wth + 3 * FF, wth + 4 * FF, nullptr,
        wtl + 3 * FF, wtl + 4 * FF, nullptr,
        b_loop_item, out_item, NNODE);
}

// round 5
// speedup vs baseline: 2.8838x; 1.6115x over previous
#include <cuda_runtime.h>
#include <cuda_bf16.h>
#include <cstdint>

#define NNODE 50000
#define F 128
#define NBLK 49            // ceil(NNODE / 1024)
#define MAXE_TOT 2000000   // capacity for all 3 relations' edges

// Scratch (sanctioned __device__ globals)
__device__ float g_agg[3ull * NNODE * F];        // normalized aggregation [rel][node][feat]
__device__ __nv_bfloat16 g_WThi[5ull * F * F];   // WT hi: [slot][n][k] = bf16(W[k][n])
__device__ __nv_bfloat16 g_WTlo[5ull * F * F];   // WT lo: residual
__device__ int g_cnt[3 * NNODE];                 // histogram
__device__ int g_part[3 * NNODE];                // per-block partial exclusive scan
__device__ int g_off[3 * (NNODE + 1)];           // CSR offsets
__device__ int g_woff[3 * NNODE];                // writable offsets for fill
__device__ int g_bs[3 * NBLK];                   // block sums for scan
__device__ int g_csr[MAXE_TOT];                  // CSR src indices (rel-concatenated)
__device__ int g_is64;

// ---------------------------------------------------------------------------
// dtype detection (int64 vs int32 edge indices)
// ---------------------------------------------------------------------------
__global__ void detect_kernel(const unsigned* __restrict__ w) {
    __shared__ int nz;
    if (threadIdx.x == 0) nz = 0;
    __syncthreads();
    if (w[2 * threadIdx.x + 1] != 0) atomicOr(&nz, 1);
    __syncthreads();
    if (threadIdx.x == 0) g_is64 = (nz == 0);
}

__global__ void zero_cnt_kernel() {
    int gid = blockIdx.x * blockDim.x + threadIdx.x;
    if (gid < 3 * NNODE) g_cnt[gid] = 0;
}

// ---------------------------------------------------------------------------
// Edge decode helper macro-ish logic shared by hist/fill: thread per edge.
// ---------------------------------------------------------------------------
__global__ void hist_kernel(const void* __restrict__ e0, const void* __restrict__ e1,
                            const void* __restrict__ e2, int E0, int E1, int E2) {
    long long gid = (long long)blockIdx.x * blockDim.x + threadIdx.x;
    const void* e; int rel; long long i; int E;
    if (gid < E0)                           { e = e0; rel = 0; i = gid;            E = E0; }
    else if (gid < (long long)E0 + E1)      { e = e1; rel = 1; i = gid - E0;       E = E1; }
    else if (gid < (long long)E0 + E1 + E2) { e = e2; rel = 2; i = gid - E0 - E1;  E = E2; }
    else return;
    long long d;
    if (g_is64) d = ((const long long*)e)[(long long)E + i];
    else        d = ((const int*)e)[E + i];
    atomicAdd(&g_cnt[rel * NNODE + (int)d], 1);
}

// scan stage 1: per-1024-block exclusive scan of g_cnt -> g_part, totals -> g_bs
__global__ void scan1_kernel() {
    int rel = blockIdx.x / NBLK, blk = blockIdx.x % NBLK;
    int d = blk * 1024 + threadIdx.x;
    int v = (d < NNODE) ? g_cnt[rel * NNODE + d] : 0;
    int lane = threadIdx.x & 31, w = threadIdx.x >> 5;
    int inc = v;
#pragma unroll
    for (int o = 1; o < 32; o <<= 1) {
        int t = __shfl_up_sync(0xFFFFFFFFu, inc, o);
        if (lane >= o) inc += t;
    }
    __shared__ int wsum[32];
    if (lane == 31) wsum[w] = inc;
    __syncthreads();
    if (w == 0) {
        int t = wsum[lane];
#pragma unroll
        for (int o = 1; o < 32; o <<= 1) {
            int u = __shfl_up_sync(0xFFFFFFFFu, t, o);
            if (lane >= o) t += u;
        }
        wsum[lane] = t;
    }
    __syncthreads();
    int base = (w > 0) ? wsum[w - 1] : 0;
    if (d < NNODE) g_part[rel * NNODE + d] = base + inc - v;
    if (threadIdx.x == 1023) g_bs[rel * NBLK + blk] = base + inc;
}

// scan stage 2: serial scan of block sums (3 x NBLK, trivial)
__global__ void scan2_kernel() {
    int tid = threadIdx.x;
    if (tid < 3) {
        int run = 0;
        for (int b = 0; b < NBLK; b++) {
            int t = g_bs[tid * NBLK + b];
            g_bs[tid * NBLK + b] = run;
            run += t;
        }
    }
}

// scan stage 3: finalize offsets (fresh write each launch - graph-replay safe)
__global__ void scan3_kernel(int E0, int E1, int E2) {
    int gid = blockIdx.x * blockDim.x + threadIdx.x;
    if (gid >= 3 * (NNODE + 1)) return;
    int rel = gid / (NNODE + 1), d = gid - rel * (NNODE + 1);
    if (d < NNODE) {
        int o = g_part[rel * NNODE + d] + g_bs[rel * NBLK + (d >> 10)];
        g_off[gid] = o;
        g_woff[rel * NNODE + d] = o;
    } else {
        g_off[gid] = (rel == 0) ? E0 : (rel == 1) ? E1 : E2;
    }
}

__global__ void fill_kernel(const void* __restrict__ e0, const void* __restrict__ e1,
                            const void* __restrict__ e2, int E0, int E1, int E2) {
    long long gid = (long long)blockIdx.x * blockDim.x + threadIdx.x;
    const void* e; int rel; long long i; int E; int base;
    if (gid < E0)                           { e = e0; rel = 0; i = gid;           E = E0; base = 0; }
    else if (gid < (long long)E0 + E1)      { e = e1; rel = 1; i = gid - E0;      E = E1; base = E0; }
    else if (gid < (long long)E0 + E1 + E2) { e = e2; rel = 2; i = gid - E0 - E1; E = E2; base = E0 + E1; }
    else return;
    long long s, d;
    if (g_is64) {
        const long long* p = (const long long*)e;
        s = p[i]; d = p[(long long)E + i];
    } else {
        const int* p = (const int*)e;
        s = p[i]; d = p[E + i];
    }
    int pos = atomicAdd(&g_woff[rel * NNODE + (int)d], 1);
    g_csr[base + pos] = (int)s;
}

// ---------------------------------------------------------------------------
// Gather-aggregate: one warp per (rel, dst). Reads CSR list, accumulates the
// mean of source rows in registers, writes the normalized row once. No atomics.
// ---------------------------------------------------------------------------
__global__ void __launch_bounds__(256) aggregate_kernel(
    const float* __restrict__ xu, const float* __restrict__ xi, int E0, int E1) {
    int lane = threadIdx.x & 31;
    int wid = (int)(((long long)blockIdx.x * blockDim.x + threadIdx.x) >> 5);
    if (wid >= 3 * NNODE) return;
    int rel = wid / NNODE;
    int beg = g_off[wid + rel];       // rel*(NNODE+1)+d == wid+rel
    int end = g_off[wid + rel + 1];
    const float* x = (rel == 1) ? xi : xu;
    const int* csr = g_csr + ((rel == 0) ? 0 : (rel == 1) ? E0 : (E0 + E1));

    float4 acc = make_float4(0.f, 0.f, 0.f, 0.f);
    int j = beg;
    for (; j + 4 <= end; j += 4) {
        int s0 = __ldg(csr + j), s1 = __ldg(csr + j + 1);
        int s2 = __ldg(csr + j + 2), s3 = __ldg(csr + j + 3);
        float4 v0 = __ldg((const float4*)(x + (size_t)s0 * F) + lane);
        float4 v1 = __ldg((const float4*)(x + (size_t)s1 * F) + lane);
        float4 v2 = __ldg((const float4*)(x + (size_t)s2 * F) + lane);
        float4 v3 = __ldg((const float4*)(x + (size_t)s3 * F) + lane);
        acc.x += (v0.x + v1.x) + (v2.x + v3.x);
        acc.y += (v0.y + v1.y) + (v2.y + v3.y);
        acc.z += (v0.z + v1.z) + (v2.z + v3.z);
        acc.w += (v0.w + v1.w) + (v2.w + v3.w);
    }
    for (; j < end; j++) {
        int s0 = __ldg(csr + j);
        float4 v0 = __ldg((const float4*)(x + (size_t)s0 * F) + lane);
        acc.x += v0.x; acc.y += v0.y; acc.z += v0.z; acc.w += v0.w;
    }
    float inv = 1.f / fmaxf((float)(end - beg), 1.f);
    acc.x *= inv; acc.y *= inv; acc.z *= inv; acc.w *= inv;
    ((float4*)(g_agg + (size_t)wid * F))[lane] = acc;
}

// ---------------------------------------------------------------------------
// Transpose + bf16 hi/lo split of the 5 weight matrices.
// ---------------------------------------------------------------------------
__global__ void convW_kernel(const float* __restrict__ W0, const float* __restrict__ W1,
                             const float* __restrict__ W2, const float* __restrict__ W3,
                             const float* __restrict__ W4) {
    const float* W = (blockIdx.x == 0) ? W0 : (blockIdx.x == 1) ? W1 :
                     (blockIdx.x == 2) ? W2 : (blockIdx.x == 3) ? W3 : W4;
    __nv_bfloat16* hi = g_WThi + (size_t)blockIdx.x * F * F;
    __nv_bfloat16* lo = g_WTlo + (size_t)blockIdx.x * F * F;
    for (int idx = threadIdx.x; idx < F * F; idx += blockDim.x) {
        int k = idx >> 7, n = idx & 127;
        float v = W[idx];
        __nv_bfloat16 h = __float2bfloat16(v);
        float r = v - __bfloat162float(h);
        hi[n * F + k] = h;
        lo[n * F + k] = __float2bfloat16(r);
    }
}

// ---------------------------------------------------------------------------
// Tensor-core GEMM via mma.sync bf16, 3-term split (hi*hi + lo*hi + hi*lo):
//   out = relu( sum_s A_s @ W_s + bias )     (A_s already normalized)
// CTA tile 128x128, 8 warps (2x4), warp tile 64x32, m16n8k16 atoms.
// ---------------------------------------------------------------------------
#define ASTRIDE 40

__device__ __forceinline__ void mma_bf16(float& c0, float& c1, float& c2, float& c3,
                                         uint32_t a0, uint32_t a1, uint32_t a2, uint32_t a3,
                                         uint32_t b0, uint32_t b1) {
    asm volatile(
        "mma.sync.aligned.m16n8k16.row.col.f32.bf16.bf16.f32 "
        "{%0,%1,%2,%3}, {%4,%5,%6,%7}, {%8,%9}, {%0,%1,%2,%3};"
        : "+f"(c0), "+f"(c1), "+f"(c2), "+f"(c3)
        : "r"(a0), "r"(a1), "r"(a2), "r"(a3), "r"(b0), "r"(b1));
}

template <int NSRC>
__global__ void __launch_bounds__(256, 2) gemm_mma(
    const float* __restrict__ A0, const float* __restrict__ A1, const float* __restrict__ A2,
    const __nv_bfloat16* __restrict__ Bh0, const __nv_bfloat16* __restrict__ Bh1,
    const __nv_bfloat16* __restrict__ Bh2,
    const __nv_bfloat16* __restrict__ Bl0, const __nv_bfloat16* __restrict__ Bl1,
    const __nv_bfloat16* __restrict__ Bl2,
    const float* __restrict__ bias, float* __restrict__ out, int M)
{
    __shared__ __nv_bfloat16 sAhi[128 * ASTRIDE];
    __shared__ __nv_bfloat16 sAlo[128 * ASTRIDE];
    __shared__ __nv_bfloat16 sBhi[128 * ASTRIDE];
    __shared__ __nv_bfloat16 sBlo[128 * ASTRIDE];

    const int tid = threadIdx.x;
    const int w = tid >> 5, l = tid & 31;
    const int mBase = (w >> 2) * 64;
    const int nBase = (w & 3) * 32;
    const int row0 = blockIdx.x * 128;
    const int lq = l >> 2;
    const int lr2 = (l & 3) * 2;

    float acc[4][4][4];
#pragma unroll
    for (int i = 0; i < 4; i++)
#pragma unroll
        for (int j = 0; j < 4; j++)
#pragma unroll
            for (int q = 0; q < 4; q++) acc[i][j][q] = 0.f;

#pragma unroll
    for (int s = 0; s < NSRC; s++) {
        const float* A = (s == 0) ? A0 : (s == 1) ? A1 : A2;
        const __nv_bfloat16* Bh = (s == 0) ? Bh0 : (s == 1) ? Bh1 : Bh2;
        const __nv_bfloat16* Bl = (s == 0) ? Bl0 : (s == 1) ? Bl1 : Bl2;

        for (int ks = 0; ks < F; ks += 32) {
            // ---- stage A chunk [128 x 32] fp32 -> hi/lo bf16 ----
#pragma unroll
            for (int t = 0; t < 4; t++) {
                int idx = t * 256 + tid;
                int r = idx >> 3, c4 = idx & 7;
                float4 v = make_float4(0.f, 0.f, 0.f, 0.f);
                int gr = row0 + r;
                if (gr < M) v = __ldg((const float4*)(A + (size_t)gr * F + ks) + c4);
                __nv_bfloat16 hx = __float2bfloat16(v.x), hy = __float2bfloat16(v.y);
                __nv_bfloat16 hz = __float2bfloat16(v.z), hw = __float2bfloat16(v.w);
                __nv_bfloat162 h01{hx, hy}, h23{hz, hw};
                __nv_bfloat162 l01{__float2bfloat16(v.x - __bfloat162float(hx)),
                                   __float2bfloat16(v.y - __bfloat162float(hy))};
                __nv_bfloat162 l23{__float2bfloat16(v.z - __bfloat162float(hz)),
                                   __float2bfloat16(v.w - __bfloat162float(hw))};
                int o = r * ASTRIDE + c4 * 4;
                *(__nv_bfloat162*)&sAhi[o] = h01;  *(__nv_bfloat162*)&sAhi[o + 2] = h23;
                *(__nv_bfloat162*)&sAlo[o] = l01;  *(__nv_bfloat162*)&sAlo[o + 2] = l23;
            }
            // ---- stage B chunk [128n x 32k] pre-split bf16 ----
#pragma unroll
            for (int t = 0; t < 4; t++) {
                int idx = t * 256 + tid;
                int n = idx >> 3, c4 = idx & 7;
                uint2 hv = *(const uint2*)(Bh + (size_t)n * F + ks + c4 * 4);
                uint2 lv = *(const uint2*)(Bl + (size_t)n * F + ks + c4 * 4);
                int o = n * ASTRIDE + c4 * 4;
                *(uint2*)&sBhi[o] = hv;
                *(uint2*)&sBlo[o] = lv;
            }
            __syncthreads();

#pragma unroll
            for (int kk = 0; kk < 32; kk += 16) {
#pragma unroll
                for (int term = 0; term < 3; term++) {
                    const __nv_bfloat16* pA = (term == 1) ? sAlo : sAhi;
                    const __nv_bfloat16* pB = (term == 2) ? sBlo : sBhi;
                    uint32_t a[4][4], b[4][2];
#pragma unroll
                    for (int i = 0; i < 4; i++) {
                        int ar = mBase + i * 16 + lq;
                        int ac = kk + lr2;
                        a[i][0] = *(const uint32_t*)&pA[ar * ASTRIDE + ac];
                        a[i][1] = *(const uint32_t*)&pA[(ar + 8) * ASTRIDE + ac];
                        a[i][2] = *(const uint32_t*)&pA[ar * ASTRIDE + ac + 8];
                        a[i][3] = *(const uint32_t*)&pA[(ar + 8) * ASTRIDE + ac + 8];
                    }
#pragma unroll
                    for (int j = 0; j < 4; j++) {
                        int bn = nBase + j * 8 + lq;
                        int bk = kk + lr2;
                        b[j][0] = *(const uint32_t*)&pB[bn * ASTRIDE + bk];
                        b[j][1] = *(const uint32_t*)&pB[bn * ASTRIDE + bk + 8];
                    }
#pragma unroll
                    for (int i = 0; i < 4; i++)
#pragma unroll
                        for (int j = 0; j < 4; j++)
                            mma_bf16(acc[i][j][0], acc[i][j][1], acc[i][j][2], acc[i][j][3],
                                     a[i][0], a[i][1], a[i][2], a[i][3], b[j][0], b[j][1]);
                }
            }
            __syncthreads();
        }
    }

    // ---- epilogue: bias + relu + store ----
#pragma unroll
    for (int j = 0; j < 4; j++) {
        int col = nBase + j * 8 + lr2;
        float2 bv = *(const float2*)(bias + col);
#pragma unroll
        for (int i = 0; i < 4; i++) {
            int r0 = row0 + mBase + i * 16 + lq;
            int r1 = r0 + 8;
            if (r0 < M) {
                float2 o0;
                o0.x = fmaxf(acc[i][j][0] + bv.x, 0.f);
                o0.y = fmaxf(acc[i][j][1] + bv.y, 0.f);
                *(float2*)(out + (size_t)r0 * F + col) = o0;
            }
            if (r1 < M) {
                float2 o1;
                o1.x = fmaxf(acc[i][j][2] + bv.x, 0.f);
                o1.y = fmaxf(acc[i][j][3] + bv.y, 0.f);
                *(float2*)(out + (size_t)r1 * F + col) = o1;
            }
        }
    }
}

// ---------------------------------------------------------------------------
extern "C" void kernel_launch(void* const* d_in, const int* in_sizes, int n_in,
                              void* d_out, int out_size) {
    const float* x_user = (const float*)d_in[0];
    const float* x_item = (const float*)d_in[1];
    const void* e_follows   = d_in[2];
    const void* e_buys      = d_in[3];
    const void* e_bought_by = d_in[4];
    const float* W_follows   = (const float*)d_in[5];
    const float* W_buys      = (const float*)d_in[6];
    const float* W_bought_by = (const float*)d_in[7];
    const float* W_loop_user = (const float*)d_in[8];
    const float* b_loop_user = (const float*)d_in[9];
    const float* W_loop_item = (const float*)d_in[10];
    const float* b_loop_item = (const float*)d_in[11];

    // Relation order for agg/CSR: 0=follows(u->u), 1=bought_by(i->u), 2=buys(u->i)
    int E0 = in_sizes[2] / 2;   // follows
    int E1 = in_sizes[4] / 2;   // bought_by
    int E2 = in_sizes[3] / 2;   // buys

    float* agg;
    __nv_bfloat16* wth; __nv_bfloat16* wtl;
    cudaGetSymbolAddress((void**)&agg, g_agg);
    cudaGetSymbolAddress((void**)&wth, g_WThi);
    cudaGetSymbolAddress((void**)&wtl, g_WTlo);

    detect_kernel<<<1, 1024>>>((const unsigned*)e_follows);
    zero_cnt_kernel<<<(3 * NNODE + 255) / 256, 256>>>();

    long long TOT = (long long)E0 + E1 + E2;
    int eblocks = (int)((TOT + 255) / 256);
    hist_kernel<<<eblocks, 256>>>(e_follows, e_bought_by, e_buys, E0, E1, E2);
    scan1_kernel<<<3 * NBLK, 1024>>>();
    scan2_kernel<<<1, 32>>>();
    scan3_kernel<<<(3 * (NNODE + 1) + 255) / 256, 256>>>(E0, E1, E2);
    fill_kernel<<<eblocks, 256>>>(e_follows, e_bought_by, e_buys, E0, E1, E2);

    aggregate_kernel<<<(3 * NNODE * 32 + 255) / 256, 256>>>(x_user, x_item, E0, E1);

    // slots: 0=follows, 1=bought_by, 2=loop_user, 3=buys, 4=loop_item
    convW_kernel<<<5, 256>>>(W_follows, W_bought_by, W_loop_user, W_buys, W_loop_item);

    float* out_user = (float*)d_out;
    float* out_item = (float*)d_out + (size_t)NNODE * F;
    int gblocks = (NNODE + 127) / 128;
    const size_t FF = (size_t)F * F;

    gemm_mma<3><<<gblocks, 256>>>(
        agg, agg + 1ll * NNODE * F, x_user,
        wth + 0 * FF, wth + 1 * FF, wth + 2 * FF,
        wtl + 0 * FF, wtl + 1 * FF, wtl + 2 * FF,
        b_loop_user, out_user, NNODE);

    gemm_mma<2><<<gblocks, 256>>>(
        agg + 2ll * NNODE * F, x_item, nullptr,
        wth + 3 * FF, wth + 4 * FF, nullptr,
        wtl + 3 * FF, wtl + 4 * FF, nullptr,
        b_loop_item, out_item, NNODE);
}